// round 1
// baseline (speedup 1.0000x reference)
#include <cuda_runtime.h>

// Problem shape (fixed by the dataset)
constexpr int T = 32, C = 3, H = 720, W = 1280;
constexpr int N = T - 2;                 // 30
constexpr long long HW = (long long)H * W;  // 921600
constexpr int W4 = W / 4;                // 320

__global__ __launch_bounds__(256)
void flowdiff_kernel(const float* __restrict__ x,
                     const float* __restrict__ flow,
                     float* __restrict__ out)
{
    int idx = blockIdx.x * blockDim.x + threadIdx.x;
    const int total = N * H * W4;
    if (idx >= total) return;

    int w4 = idx % W4;
    int h  = (idx / W4) % H;
    int n  = idx / (W4 * H);
    int w  = w4 * 4;
    long long hw = (long long)h * W + w;

    // Flow loads: fully coalesced float4
    const float4 f0 = *(const float4*)(flow + ((long long)(2 * n)     ) * HW + hw); // fwd dx (row)
    const float4 f1 = *(const float4*)(flow + ((long long)(2 * n) + 1 ) * HW + hw); // fwd dy (col)
    const int nb = N - 1 - n;
    const float4 b0 = *(const float4*)(flow + ((long long)(2 * nb)    ) * HW + hw);
    const float4 b1 = *(const float4*)(flow + ((long long)(2 * nb) + 1) * HW + hw);

    // Rounded + clamped gather offsets (row*W + col) for 4 lanes, fwd and bwd.
    int offF[4], offB[4];
    {
        const float fh = (float)h;
        float fx[4] = {f0.x, f0.y, f0.z, f0.w};
        float fy[4] = {f1.x, f1.y, f1.z, f1.w};
        float bx[4] = {b0.x, b0.y, b0.z, b0.w};
        float by[4] = {b1.x, b1.y, b1.z, b1.w};
#pragma unroll
        for (int j = 0; j < 4; ++j) {
            int ihf = __float2int_rn(fh + fx[j]);
            ihf = min(max(ihf, 0), H - 1);
            int iwf = __float2int_rn((float)(w + j) + fy[j]);
            iwf = min(max(iwf, 0), W - 1);
            offF[j] = ihf * W + iwf;

            int ihb = __float2int_rn(fh + bx[j]);
            ihb = min(max(ihb, 0), H - 1);
            int iwb = __float2int_rn((float)(w + j) + by[j]);
            iwb = min(max(iwb, 0), W - 1);
            offB[j] = ihb * W + iwb;
        }
    }

    const float* __restrict__ xC = x + (long long)(n + 1) * C * HW;  // center frame
    const float* __restrict__ xF = x + (long long)(n + 2) * C * HW;  // fwd-gather frame
    const float* __restrict__ xB = x + (long long)(n    ) * C * HW;  // bwd-gather frame
    float* __restrict__ oBase = out + (long long)n * 6 * HW + hw;

#pragma unroll
    for (int c = 0; c < C; ++c) {
        const long long cHW = (long long)c * HW;
        const float4 xc = *(const float4*)(xC + cHW + hw);

        float4 of, ob;
        of.x = xc.x - __ldg(xF + cHW + offF[0]);
        of.y = xc.y - __ldg(xF + cHW + offF[1]);
        of.z = xc.z - __ldg(xF + cHW + offF[2]);
        of.w = xc.w - __ldg(xF + cHW + offF[3]);

        ob.x = xc.x - __ldg(xB + cHW + offB[0]);
        ob.y = xc.y - __ldg(xB + cHW + offB[1]);
        ob.z = xc.z - __ldg(xB + cHW + offB[2]);
        ob.w = xc.w - __ldg(xB + cHW + offB[3]);

        *(float4*)(oBase + (long long)c * HW)       = of;
        *(float4*)(oBase + (long long)(3 + c) * HW) = ob;
    }
}

extern "C" void kernel_launch(void* const* d_in, const int* in_sizes, int n_in,
                              void* d_out, int out_size)
{
    const float* x    = (const float*)d_in[0];
    const float* flow = (const float*)d_in[1];
    float* out        = (float*)d_out;

    const int total = N * H * W4;           // 6,912,000 thread-groups
    const int threads = 256;
    const int blocks = (total + threads - 1) / threads;
    flowdiff_kernel<<<blocks, threads>>>(x, flow, out);
}